// round 2
// baseline (speedup 1.0000x reference)
#include <cuda_runtime.h>

#define NN 10000
#define NE 320000
#define F_IN 128
#define F_HID 256

// ---------------- scratch (device globals; no allocation allowed) ----------------
__device__ int   g_deg[NN];          // out-degree (by src)
__device__ int   g_incnt[NN];        // in-degree  (by dst)
__device__ int   g_roff[NN + 1];     // CSR row offsets (by dst)
__device__ int   g_rank[NE];         // rank of edge within its dst bucket
__device__ float g_inv[NN];          // 1/out-degree
__device__ int   g_csr_src[NE];
__device__ float g_csr_w[NE];
__device__ float g_bufA[NN * F_HID];
__device__ float g_bufB[NN * F_HID];
__device__ float g_vsum;

// ---------------- packed f32x2 helpers ----------------
__device__ __forceinline__ void fma2(unsigned long long& acc, unsigned long long a,
                                     unsigned long long b) {
    asm("fma.rn.f32x2 %0, %1, %2, %0;" : "+l"(acc) : "l"(a), "l"(b));
}
__device__ __forceinline__ unsigned long long pack2(float x) {
    unsigned long long r;
    asm("mov.b64 %0, {%1, %1};" : "=l"(r) : "f"(x));
    return r;
}
__device__ __forceinline__ void unpack2(unsigned long long v, float& lo, float& hi) {
    asm("mov.b64 {%0, %1}, %2;" : "=f"(lo), "=f"(hi) : "l"(v));
}

// ---------------- graph preprocessing ----------------
__global__ void zero_kernel() {
    int i = blockIdx.x * blockDim.x + threadIdx.x;
    if (i < NN) { g_deg[i] = 0; g_incnt[i] = 0; }
    if (i == 0) g_vsum = 0.0f;
}

__global__ void count_kernel(const int* __restrict__ src, const int* __restrict__ dst) {
    int e = blockIdx.x * blockDim.x + threadIdx.x;
    if (e < NE) {
        atomicAdd(&g_deg[src[e]], 1);
        g_rank[e] = atomicAdd(&g_incnt[dst[e]], 1);
    }
}

// single-block exclusive scan over in-degree counts -> row offsets + inv-deg
__global__ void scan_kernel() {
    __shared__ int carry;
    __shared__ int wsum[32];
    int tid = threadIdx.x;  // 1024 threads
    if (tid == 0) carry = 0;
    __syncthreads();
    for (int base = 0; base < NN; base += 1024) {
        int i = base + tid;
        int v = (i < NN) ? g_incnt[i] : 0;
        int x = v;
        #pragma unroll
        for (int o = 1; o < 32; o <<= 1) {
            int y = __shfl_up_sync(0xffffffffu, x, o);
            if ((tid & 31) >= o) x += y;
        }
        if ((tid & 31) == 31) wsum[tid >> 5] = x;
        __syncthreads();
        if (tid < 32) {
            int s = wsum[tid];
            int t = s;
            #pragma unroll
            for (int o = 1; o < 32; o <<= 1) {
                int y = __shfl_up_sync(0xffffffffu, t, o);
                if (tid >= o) t += y;
            }
            wsum[tid] = t - s;  // exclusive warp offset
        }
        __syncthreads();
        int incl = x + wsum[tid >> 5] + carry;
        if (i < NN) g_roff[i + 1] = incl;
        __syncthreads();
        if (tid == 1023) carry = incl;
        __syncthreads();
    }
    if (tid == 0) g_roff[0] = 0;
    for (int i = tid; i < NN; i += 1024) {
        int d = g_deg[i];
        g_inv[i] = (d > 0) ? 1.0f / (float)d : 0.0f;
    }
}

// atomic-free fill: position = roff[dst] + rank (rank captured during count)
__global__ void fill_kernel(const int* __restrict__ src, const int* __restrict__ dst) {
    int e = blockIdx.x * blockDim.x + threadIdx.x;
    if (e < NE) {
        int d = dst[e];
        int s = src[e];
        int p = g_roff[d] + g_rank[e];
        g_csr_src[p] = s;
        g_csr_w[p]   = g_inv[s];
    }
}

// ---------------- edge aggregation: Y[d] = sum_{e: dst=d} w_e * X[src_e] ----------------
template <int CHUNKS>
__global__ void aggregate_kernel(const float* __restrict__ X, float* __restrict__ Y, int F) {
    int gw    = (blockIdx.x * blockDim.x + threadIdx.x) >> 5;
    int lane  = threadIdx.x & 31;
    int nwrp  = (gridDim.x * blockDim.x) >> 5;
    for (int n = gw; n < NN; n += nwrp) {
        int s0 = g_roff[n], s1 = g_roff[n + 1];
        float4 acc0 = make_float4(0.f, 0.f, 0.f, 0.f);
        float4 acc1 = make_float4(0.f, 0.f, 0.f, 0.f);
        for (int e0 = s0; e0 < s1; e0 += 32) {
            int e = e0 + lane;
            int   ss = 0; float ww = 0.f;
            if (e < s1) { ss = g_csr_src[e]; ww = g_csr_w[e]; }
            int cnt = min(32, s1 - e0);
            for (int j = 0; j < cnt; j++) {
                int   sj = __shfl_sync(0xffffffffu, ss, j);
                float wj = __shfl_sync(0xffffffffu, ww, j);
                const float4* xp = (const float4*)(X + (size_t)sj * F);
                float4 v0 = xp[lane];
                acc0.x += wj * v0.x; acc0.y += wj * v0.y;
                acc0.z += wj * v0.z; acc0.w += wj * v0.w;
                if (CHUNKS == 2) {
                    float4 v1 = xp[lane + 32];
                    acc1.x += wj * v1.x; acc1.y += wj * v1.y;
                    acc1.z += wj * v1.z; acc1.w += wj * v1.w;
                }
            }
        }
        float4* yp = (float4*)(Y + (size_t)n * F);
        yp[lane] = acc0;
        if (CHUNKS == 2) yp[lane + 32] = acc1;
    }
}

// ---------------- C = act(A[M,K] @ W[K,256] + b), packed f32x2 FMA ----------------
// 64x128 block tile, 256 threads, micro-tile 4 rows x 8 cols (4 f32x2 pairs), BK=16
__global__ void gemm_bias_act(const float* __restrict__ A, const float* __restrict__ W,
                              const float* __restrict__ bias, float* __restrict__ C,
                              int M, int K, int relu) {
    __shared__ __align__(16) float As[16][68];   // [k][m], padded
    __shared__ __align__(16) float Bs[16][128];  // [k][n]
    int tid = threadIdx.x;
    int bm0 = blockIdx.x * 64;
    int bn0 = blockIdx.y * 128;
    int tx = tid & 15;        // col group: 8 cols each
    int ty = tid >> 4;        // row group: 4 rows each

    int arow = tid >> 2;           // 0..63
    int acol = (tid & 3) * 4;      // 0,4,8,12
    int brow = tid >> 4;           // 0..15
    int bcol = (tid & 15) * 8;     // 0..120

    unsigned long long acc[4][4];
    #pragma unroll
    for (int i = 0; i < 4; i++)
        #pragma unroll
        for (int j = 0; j < 4; j++) acc[i][j] = 0ull;

    for (int k0 = 0; k0 < K; k0 += 16) {
        float4 av = make_float4(0.f, 0.f, 0.f, 0.f);
        if (bm0 + arow < M)
            av = *(const float4*)(A + (size_t)(bm0 + arow) * K + k0 + acol);
        As[acol + 0][arow] = av.x;
        As[acol + 1][arow] = av.y;
        As[acol + 2][arow] = av.z;
        As[acol + 3][arow] = av.w;
        const float* wrow = W + (size_t)(k0 + brow) * 256 + bn0 + bcol;
        *(float4*)&Bs[brow][bcol]     = *(const float4*)(wrow);
        *(float4*)&Bs[brow][bcol + 4] = *(const float4*)(wrow + 4);
        __syncthreads();
        #pragma unroll
        for (int kk = 0; kk < 16; kk++) {
            float4 a = *(const float4*)&As[kk][ty * 4];
            ulonglong2 b0 = *(const ulonglong2*)&Bs[kk][tx * 8];
            ulonglong2 b1 = *(const ulonglong2*)&Bs[kk][tx * 8 + 4];
            unsigned long long ap[4];
            ap[0] = pack2(a.x); ap[1] = pack2(a.y);
            ap[2] = pack2(a.z); ap[3] = pack2(a.w);
            unsigned long long bp_[4] = {b0.x, b0.y, b1.x, b1.y};
            #pragma unroll
            for (int i = 0; i < 4; i++)
                #pragma unroll
                for (int j = 0; j < 4; j++)
                    fma2(acc[i][j], ap[i], bp_[j]);
        }
        __syncthreads();
    }

    #pragma unroll
    for (int i = 0; i < 4; i++) {
        int r = bm0 + ty * 4 + i;
        if (r < M) {
            int c0 = bn0 + tx * 8;
            float v[8];
            #pragma unroll
            for (int j = 0; j < 4; j++) unpack2(acc[i][j], v[j * 2], v[j * 2 + 1]);
            #pragma unroll
            for (int j = 0; j < 8; j++) {
                v[j] += bias[c0 + j];
                if (relu) v[j] = fmaxf(v[j], 0.f);
            }
            float4* cp = (float4*)(C + (size_t)r * 256 + c0);
            cp[0] = make_float4(v[0], v[1], v[2], v[3]);
            cp[1] = make_float4(v[4], v[5], v[6], v[7]);
        }
    }
}

// ---------------- heads: PI[n] = h3[n].Wp + bp ; vsum += h3[n].Wv ----------------
__global__ void heads_kernel(const float* __restrict__ H, const float* __restrict__ Wp,
                             const float* __restrict__ bp, const float* __restrict__ Wv,
                             float* __restrict__ out) {
    int gw   = (blockIdx.x * blockDim.x + threadIdx.x) >> 5;
    int lane = threadIdx.x & 31;
    int nwrp = (gridDim.x * blockDim.x) >> 5;
    const float4* p4 = (const float4*)Wp;
    const float4* v4 = (const float4*)Wv;
    for (int n = gw; n < NN; n += nwrp) {
        const float4* h4 = (const float4*)(H + (size_t)n * 256);
        float4 h0 = h4[lane], h1 = h4[lane + 32];
        float4 a0 = p4[lane], a1 = p4[lane + 32];
        float4 b0 = v4[lane], b1 = v4[lane + 32];
        float dp = h0.x * a0.x + h0.y * a0.y + h0.z * a0.z + h0.w * a0.w
                 + h1.x * a1.x + h1.y * a1.y + h1.z * a1.z + h1.w * a1.w;
        float dv = h0.x * b0.x + h0.y * b0.y + h0.z * b0.z + h0.w * b0.w
                 + h1.x * b1.x + h1.y * b1.y + h1.z * b1.z + h1.w * b1.w;
        #pragma unroll
        for (int o = 16; o > 0; o >>= 1) {
            dp += __shfl_xor_sync(0xffffffffu, dp, o);
            dv += __shfl_xor_sync(0xffffffffu, dv, o);
        }
        if (lane == 0) {
            out[n] = dp + bp[0];
            atomicAdd(&g_vsum, dv);
        }
    }
}

__global__ void final_kernel(const float* __restrict__ bv, float* __restrict__ out) {
    if (threadIdx.x == 0)
        out[NN] = g_vsum * (1.0f / (float)NN) + bv[0];
}

// ---------------- launch ----------------
extern "C" void kernel_launch(void* const* d_in, const int* in_sizes, int n_in,
                              void* d_out, int out_size) {
    const float* features = (const float*)d_in[0];
    const int*   src      = (const int*)d_in[1];
    const int*   dst      = (const int*)d_in[2];
    const float* W1 = (const float*)d_in[3];
    const float* b1 = (const float*)d_in[4];
    const float* W2 = (const float*)d_in[5];
    const float* b2 = (const float*)d_in[6];
    const float* W3 = (const float*)d_in[7];
    const float* b3 = (const float*)d_in[8];
    const float* Wp = (const float*)d_in[9];
    const float* bp = (const float*)d_in[10];
    const float* Wv = (const float*)d_in[11];
    const float* bv = (const float*)d_in[12];
    float* out = (float*)d_out;

    void *pA_, *pB_;
    cudaGetSymbolAddress(&pA_, g_bufA);
    cudaGetSymbolAddress(&pB_, g_bufB);
    float* bufA = (float*)pA_;
    float* bufB = (float*)pB_;

    // graph preprocessing (CSR by dst, left-normalization weights)
    zero_kernel<<<(NN + 255) / 256, 256>>>();
    count_kernel<<<(NE + 255) / 256, 256>>>(src, dst);
    scan_kernel<<<1, 1024>>>();
    fill_kernel<<<(NE + 255) / 256, 256>>>(src, dst);

    dim3 ggrid((NN + 63) / 64, 2);

    // layer 1: aggregate(features) [N,128] -> GEMM W1 + relu -> [N,256]
    aggregate_kernel<1><<<1250, 256>>>(features, bufA, 128);
    gemm_bias_act<<<ggrid, 256>>>(bufA, W1, b1, bufB, NN, 128, 1);
    // layer 2
    aggregate_kernel<2><<<1250, 256>>>(bufB, bufA, 256);
    gemm_bias_act<<<ggrid, 256>>>(bufA, W2, b2, bufB, NN, 256, 1);
    // layer 3 (no activation)
    aggregate_kernel<2><<<1250, 256>>>(bufB, bufA, 256);
    gemm_bias_act<<<ggrid, 256>>>(bufA, W3, b3, bufB, NN, 256, 0);

    // heads
    heads_kernel<<<1250, 256>>>(bufB, Wp, bp, Wv, out);
    final_kernel<<<1, 32>>>(bv, out);
}

// round 4
// speedup vs baseline: 1.6500x; 1.6500x over previous
#include <cuda_runtime.h>
#include <cuda_bf16.h>
#include <cstdint>

#define NN 10000
#define NE 320000
#define F_HID 256

// ---------------- scratch (device globals; no allocation allowed) ----------------
__device__ int   g_deg[NN];
__device__ int   g_incnt[NN];
__device__ int   g_roff[NN + 1];
__device__ int   g_rank[NE];
__device__ float g_inv[NN];
__device__ int   g_csr_src[NE];
__device__ float g_csr_w[NE];
__device__ float g_buf[NN * F_HID];                 // fp32 GEMM outputs
__device__ __nv_bfloat16 g_ahi[NN * F_HID];         // bf16 hi of GEMM input
__device__ __nv_bfloat16 g_alo[NN * F_HID];         // bf16 lo
__device__ __nv_bfloat16 g_whi[256 * 256 * 3];      // converted weights
__device__ __nv_bfloat16 g_wlo[256 * 256 * 3];
__device__ float g_vsum;

// ---------------- helpers ----------------
__device__ __forceinline__ void cvt_hilo2(float x0, float x1, uint32_t& hip, uint32_t& lop) {
    __nv_bfloat162 h = __floats2bfloat162_rn(x0, x1);
    float h0 = __bfloat162float(__low2bfloat16(h));
    float h1 = __bfloat162float(__high2bfloat16(h));
    __nv_bfloat162 l = __floats2bfloat162_rn(x0 - h0, x1 - h1);
    hip = *reinterpret_cast<uint32_t*>(&h);
    lop = *reinterpret_cast<uint32_t*>(&l);
}

__device__ __forceinline__ void ldsm4(uint32_t* r, uint32_t addr) {
    asm volatile("ldmatrix.sync.aligned.m8n8.x4.shared.b16 {%0,%1,%2,%3}, [%4];"
                 : "=r"(r[0]), "=r"(r[1]), "=r"(r[2]), "=r"(r[3]) : "r"(addr));
}
__device__ __forceinline__ void ldsm4t(uint32_t* r, uint32_t addr) {
    asm volatile("ldmatrix.sync.aligned.m8n8.x4.trans.shared.b16 {%0,%1,%2,%3}, [%4];"
                 : "=r"(r[0]), "=r"(r[1]), "=r"(r[2]), "=r"(r[3]) : "r"(addr));
}
__device__ __forceinline__ void mma16816(float* c, const uint32_t* a, const uint32_t* b) {
    asm volatile(
        "mma.sync.aligned.m16n8k16.row.col.f32.bf16.bf16.f32 "
        "{%0,%1,%2,%3}, {%4,%5,%6,%7}, {%8,%9}, {%0,%1,%2,%3};"
        : "+f"(c[0]), "+f"(c[1]), "+f"(c[2]), "+f"(c[3])
        : "r"(a[0]), "r"(a[1]), "r"(a[2]), "r"(a[3]), "r"(b[0]), "r"(b[1]));
}

// ---------------- graph preprocessing ----------------
__global__ void zero_kernel() {
    int i = blockIdx.x * blockDim.x + threadIdx.x;
    if (i < NN) { g_deg[i] = 0; g_incnt[i] = 0; }
    if (i == 0) g_vsum = 0.0f;
}

__global__ void count_kernel(const int* __restrict__ src, const int* __restrict__ dst) {
    int e = blockIdx.x * blockDim.x + threadIdx.x;
    if (e < NE) {
        atomicAdd(&g_deg[src[e]], 1);
        g_rank[e] = atomicAdd(&g_incnt[dst[e]], 1);
    }
}

__global__ void scan_kernel() {
    __shared__ int carry;
    __shared__ int wsum[32];
    int tid = threadIdx.x;  // 1024 threads
    if (tid == 0) carry = 0;
    __syncthreads();
    for (int base = 0; base < NN; base += 1024) {
        int i = base + tid;
        int v = (i < NN) ? g_incnt[i] : 0;
        int x = v;
        #pragma unroll
        for (int o = 1; o < 32; o <<= 1) {
            int y = __shfl_up_sync(0xffffffffu, x, o);
            if ((tid & 31) >= o) x += y;
        }
        if ((tid & 31) == 31) wsum[tid >> 5] = x;
        __syncthreads();
        if (tid < 32) {
            int s = wsum[tid];
            int t = s;
            #pragma unroll
            for (int o = 1; o < 32; o <<= 1) {
                int y = __shfl_up_sync(0xffffffffu, t, o);
                if (tid >= o) t += y;
            }
            wsum[tid] = t - s;
        }
        __syncthreads();
        int incl = x + wsum[tid >> 5] + carry;
        if (i < NN) g_roff[i + 1] = incl;
        __syncthreads();
        if (tid == 1023) carry = incl;
        __syncthreads();
    }
    if (tid == 0) g_roff[0] = 0;
    for (int i = tid; i < NN; i += 1024) {
        int d = g_deg[i];
        g_inv[i] = (d > 0) ? 1.0f / (float)d : 0.0f;
    }
}

__global__ void fill_kernel(const int* __restrict__ src, const int* __restrict__ dst) {
    int e = blockIdx.x * blockDim.x + threadIdx.x;
    if (e < NE) {
        int d = dst[e];
        int s = src[e];
        int p = g_roff[d] + g_rank[e];
        g_csr_src[p] = s;
        g_csr_w[p]   = g_inv[s];
    }
}

// ---------------- weight conversion fp32 -> bf16 hi/lo ----------------
__global__ void convert_w(const float* __restrict__ W, int n, int off) {
    int i = 2 * (blockIdx.x * blockDim.x + threadIdx.x);
    if (i < n) {
        float2 v = *(const float2*)(W + i);
        uint32_t hip, lop;
        cvt_hilo2(v.x, v.y, hip, lop);
        *(uint32_t*)((char*)g_whi + 2 * (off + i)) = hip;
        *(uint32_t*)((char*)g_wlo + 2 * (off + i)) = lop;
    }
}

// ---------------- edge aggregation -> bf16 hi/lo output ----------------
template <int CHUNKS>
__global__ void aggregate_kernel(const float* __restrict__ X,
                                 __nv_bfloat16* __restrict__ Yhi,
                                 __nv_bfloat16* __restrict__ Ylo, int F) {
    int gw    = (blockIdx.x * blockDim.x + threadIdx.x) >> 5;
    int lane  = threadIdx.x & 31;
    int nwrp  = (gridDim.x * blockDim.x) >> 5;
    for (int n = gw; n < NN; n += nwrp) {
        int s0 = g_roff[n], s1 = g_roff[n + 1];
        float4 acc0 = make_float4(0.f, 0.f, 0.f, 0.f);
        float4 acc1 = make_float4(0.f, 0.f, 0.f, 0.f);
        for (int e0 = s0; e0 < s1; e0 += 32) {
            int e = e0 + lane;
            int   ss = 0; float ww = 0.f;
            if (e < s1) { ss = g_csr_src[e]; ww = g_csr_w[e]; }
            int cnt = min(32, s1 - e0);
            for (int j = 0; j < cnt; j++) {
                int   sj = __shfl_sync(0xffffffffu, ss, j);
                float wj = __shfl_sync(0xffffffffu, ww, j);
                const float4* xp = (const float4*)(X + (size_t)sj * F);
                float4 v0 = xp[lane];
                acc0.x += wj * v0.x; acc0.y += wj * v0.y;
                acc0.z += wj * v0.z; acc0.w += wj * v0.w;
                if (CHUNKS == 2) {
                    float4 v1 = xp[lane + 32];
                    acc1.x += wj * v1.x; acc1.y += wj * v1.y;
                    acc1.z += wj * v1.z; acc1.w += wj * v1.w;
                }
            }
        }
        uint32_t h01, l01, h23, l23;
        cvt_hilo2(acc0.x, acc0.y, h01, l01);
        cvt_hilo2(acc0.z, acc0.w, h23, l23);
        ((uint2*)(Yhi + (size_t)n * F))[lane] = make_uint2(h01, h23);
        ((uint2*)(Ylo + (size_t)n * F))[lane] = make_uint2(l01, l23);
        if (CHUNKS == 2) {
            cvt_hilo2(acc1.x, acc1.y, h01, l01);
            cvt_hilo2(acc1.z, acc1.w, h23, l23);
            ((uint2*)(Yhi + (size_t)n * F))[lane + 32] = make_uint2(h01, h23);
            ((uint2*)(Ylo + (size_t)n * F))[lane + 32] = make_uint2(l01, l23);
        }
    }
}

// ---------------- GEMM: C = act(A[M,K] @ W[K,256] + b) via mma.sync bf16 hi/lo ----------------
// CTA tile 128x128, 8 warps (2m x 4n), warp tile 64x32, BK=32
#define AS_STRIDE 40
#define BS_STRIDE 136
__global__ void __launch_bounds__(256)
gemm_mma(const __nv_bfloat16* __restrict__ Ahi, const __nv_bfloat16* __restrict__ Alo,
         const __nv_bfloat16* __restrict__ Whi, const __nv_bfloat16* __restrict__ Wlo,
         const float* __restrict__ bias, float* __restrict__ C, int K, int relu) {
    __shared__ __align__(16) __nv_bfloat16 sAhi[128 * AS_STRIDE];
    __shared__ __align__(16) __nv_bfloat16 sAlo[128 * AS_STRIDE];
    __shared__ __align__(16) __nv_bfloat16 sBhi[32 * BS_STRIDE];
    __shared__ __align__(16) __nv_bfloat16 sBlo[32 * BS_STRIDE];
    __shared__ float sbias[128];

    int tid = threadIdx.x;
    int m0 = blockIdx.x * 128, n0 = blockIdx.y * 128;
    if (tid < 128) sbias[tid] = bias[n0 + tid];
    int wid = tid >> 5, lane = tid & 31;
    int wm = (wid & 1) * 64, wn = (wid >> 1) * 32;

    float acc[4][4][4];
    #pragma unroll
    for (int i = 0; i < 4; i++)
        #pragma unroll
        for (int j = 0; j < 4; j++)
            #pragma unroll
            for (int q = 0; q < 4; q++) acc[i][j][q] = 0.f;

    const uint4 z4 = make_uint4(0, 0, 0, 0);

    for (int kc = 0; kc < K; kc += 32) {
        // stage A (128 rows x 32 k) hi+lo
        #pragma unroll
        for (int idx = tid; idx < 512; idx += 256) {
            int row = idx >> 2, c16 = idx & 3;
            int gr = m0 + row;
            uint4 vh = z4, vl = z4;
            if (gr < NN) {
                vh = *(const uint4*)(Ahi + (size_t)gr * K + kc + c16 * 8);
                vl = *(const uint4*)(Alo + (size_t)gr * K + kc + c16 * 8);
            }
            *(uint4*)(sAhi + row * AS_STRIDE + c16 * 8) = vh;
            *(uint4*)(sAlo + row * AS_STRIDE + c16 * 8) = vl;
        }
        // stage B (32 k rows x 128 n) hi+lo
        #pragma unroll
        for (int idx = tid; idx < 512; idx += 256) {
            int row = idx >> 4, c16 = idx & 15;
            *(uint4*)(sBhi + row * BS_STRIDE + c16 * 8) =
                *(const uint4*)(Whi + (size_t)(kc + row) * 256 + n0 + c16 * 8);
            *(uint4*)(sBlo + row * BS_STRIDE + c16 * 8) =
                *(const uint4*)(Wlo + (size_t)(kc + row) * 256 + n0 + c16 * 8);
        }
        __syncthreads();

        #pragma unroll
        for (int k16 = 0; k16 < 2; k16++) {
            uint32_t ah[4][4], al[4][4], bh[4][2], bl[4][2];
            #pragma unroll
            for (int mt = 0; mt < 4; mt++) {
                int row = wm + mt * 16 + (lane & 15);
                int col = k16 * 16 + (lane >> 4) * 8;
                uint32_t ad = (uint32_t)__cvta_generic_to_shared(sAhi + row * AS_STRIDE + col);
                ldsm4(ah[mt], ad);
                ad = (uint32_t)__cvta_generic_to_shared(sAlo + row * AS_STRIDE + col);
                ldsm4(al[mt], ad);
            }
            #pragma unroll
            for (int nt2 = 0; nt2 < 2; nt2++) {
                int row = k16 * 16 + (lane & 15);
                int col = wn + nt2 * 16 + ((lane >> 4) & 1) * 8;
                uint32_t t[4];
                uint32_t ad = (uint32_t)__cvta_generic_to_shared(sBhi + row * BS_STRIDE + col);
                ldsm4t(t, ad);
                bh[nt2 * 2][0] = t[0]; bh[nt2 * 2][1] = t[1];
                bh[nt2 * 2 + 1][0] = t[2]; bh[nt2 * 2 + 1][1] = t[3];
                ad = (uint32_t)__cvta_generic_to_shared(sBlo + row * BS_STRIDE + col);
                ldsm4t(t, ad);
                bl[nt2 * 2][0] = t[0]; bl[nt2 * 2][1] = t[1];
                bl[nt2 * 2 + 1][0] = t[2]; bl[nt2 * 2 + 1][1] = t[3];
            }
            #pragma unroll
            for (int mt = 0; mt < 4; mt++)
                #pragma unroll
                for (int nt = 0; nt < 4; nt++) {
                    mma16816(acc[mt][nt], ah[mt], bh[nt]);
                    mma16816(acc[mt][nt], ah[mt], bl[nt]);
                    mma16816(acc[mt][nt], al[mt], bh[nt]);
                }
        }
        __syncthreads();
    }

    // epilogue: bias + relu, write fp32
    #pragma unroll
    for (int mt = 0; mt < 4; mt++) {
        int r0 = m0 + wm + mt * 16 + (lane >> 2);
        int r1 = r0 + 8;
        #pragma unroll
        for (int nt = 0; nt < 4; nt++) {
            int cl = wn + nt * 8 + (lane & 3) * 2;
            float b0 = sbias[cl], b1 = sbias[cl + 1];
            if (r0 < NN) {
                float v0 = acc[mt][nt][0] + b0;
                float v1 = acc[mt][nt][1] + b1;
                if (relu) { v0 = fmaxf(v0, 0.f); v1 = fmaxf(v1, 0.f); }
                *(float2*)(C + (size_t)r0 * 256 + n0 + cl) = make_float2(v0, v1);
            }
            if (r1 < NN) {
                float v2 = acc[mt][nt][2] + b0;
                float v3 = acc[mt][nt][3] + b1;
                if (relu) { v2 = fmaxf(v2, 0.f); v3 = fmaxf(v3, 0.f); }
                *(float2*)(C + (size_t)r1 * 256 + n0 + cl) = make_float2(v2, v3);
            }
        }
    }
}

// ---------------- heads ----------------
__global__ void heads_kernel(const float* __restrict__ H, const float* __restrict__ Wp,
                             const float* __restrict__ bp, const float* __restrict__ Wv,
                             float* __restrict__ out) {
    int gw   = (blockIdx.x * blockDim.x + threadIdx.x) >> 5;
    int lane = threadIdx.x & 31;
    int nwrp = (gridDim.x * blockDim.x) >> 5;
    const float4* p4 = (const float4*)Wp;
    const float4* v4 = (const float4*)Wv;
    for (int n = gw; n < NN; n += nwrp) {
        const float4* h4 = (const float4*)(H + (size_t)n * 256);
        float4 h0 = h4[lane], h1 = h4[lane + 32];
        float4 a0 = p4[lane], a1 = p4[lane + 32];
        float4 b0 = v4[lane], b1 = v4[lane + 32];
        float dp = h0.x * a0.x + h0.y * a0.y + h0.z * a0.z + h0.w * a0.w
                 + h1.x * a1.x + h1.y * a1.y + h1.z * a1.z + h1.w * a1.w;
        float dv = h0.x * b0.x + h0.y * b0.y + h0.z * b0.z + h0.w * b0.w
                 + h1.x * b1.x + h1.y * b1.y + h1.z * b1.z + h1.w * b1.w;
        #pragma unroll
        for (int o = 16; o > 0; o >>= 1) {
            dp += __shfl_xor_sync(0xffffffffu, dp, o);
            dv += __shfl_xor_sync(0xffffffffu, dv, o);
        }
        if (lane == 0) {
            out[n] = dp + bp[0];
            atomicAdd(&g_vsum, dv);
        }
    }
}

__global__ void final_kernel(const float* __restrict__ bv, float* __restrict__ out) {
    if (threadIdx.x == 0)
        out[NN] = g_vsum * (1.0f / (float)NN) + bv[0];
}

// ---------------- launch ----------------
extern "C" void kernel_launch(void* const* d_in, const int* in_sizes, int n_in,
                              void* d_out, int out_size) {
    const float* features = (const float*)d_in[0];
    const int*   src      = (const int*)d_in[1];
    const int*   dst      = (const int*)d_in[2];
    const float* W1 = (const float*)d_in[3];
    const float* b1 = (const float*)d_in[4];
    const float* W2 = (const float*)d_in[5];
    const float* b2 = (const float*)d_in[6];
    const float* W3 = (const float*)d_in[7];
    const float* b3 = (const float*)d_in[8];
    const float* Wp = (const float*)d_in[9];
    const float* bp = (const float*)d_in[10];
    const float* Wv = (const float*)d_in[11];
    const float* bv = (const float*)d_in[12];
    float* out = (float*)d_out;

    void *pBuf_, *pAhi_, *pAlo_, *pWhi_, *pWlo_;
    cudaGetSymbolAddress(&pBuf_, g_buf);
    cudaGetSymbolAddress(&pAhi_, g_ahi);
    cudaGetSymbolAddress(&pAlo_, g_alo);
    cudaGetSymbolAddress(&pWhi_, g_whi);
    cudaGetSymbolAddress(&pWlo_, g_wlo);
    float* buf = (float*)pBuf_;
    __nv_bfloat16* ahi = (__nv_bfloat16*)pAhi_;
    __nv_bfloat16* alo = (__nv_bfloat16*)pAlo_;
    __nv_bfloat16* whi = (__nv_bfloat16*)pWhi_;
    __nv_bfloat16* wlo = (__nv_bfloat16*)pWlo_;

    // graph preprocessing
    zero_kernel<<<(NN + 255) / 256, 256>>>();
    count_kernel<<<(NE + 255) / 256, 256>>>(src, dst);
    scan_kernel<<<1, 1024>>>();
    fill_kernel<<<(NE + 255) / 256, 256>>>(src, dst);

    // weight conversion (offsets in elements)
    convert_w<<<64, 256>>>(W1, 128 * 256, 0);
    convert_w<<<128, 256>>>(W2, 256 * 256, 32768);
    convert_w<<<128, 256>>>(W3, 256 * 256, 98304);

    dim3 ggrid(79, 2);

    // layer 1 (K=128)
    aggregate_kernel<1><<<1250, 256>>>(features, ahi, alo, 128);
    gemm_mma<<<ggrid, 256>>>(ahi, alo, whi, wlo, b1, buf, 128, 1);
    // layer 2 (K=256)
    aggregate_kernel<2><<<1250, 256>>>(buf, ahi, alo, 256);
    gemm_mma<<<ggrid, 256>>>(ahi, alo, whi + 32768, wlo + 32768, b2, buf, 256, 1);
    // layer 3 (K=256)
    aggregate_kernel<2><<<1250, 256>>>(buf, ahi, alo, 256);
    gemm_mma<<<ggrid, 256>>>(ahi, alo, whi + 98304, wlo + 98304, b3, buf, 256, 0);

    // heads
    heads_kernel<<<1250, 256>>>(buf, Wp, bp, Wv, out);
    final_kernel<<<1, 32>>>(bv, out);
}